// round 6
// baseline (speedup 1.0000x reference)
#include <cuda_runtime.h>
#include <math_constants.h>

#define N_OSC   60
#define BDIM    128
#define TI      10          // i-tile size (accumulator block) — R2-proven
#define NTILES  6           // 60 / 10
#define STEPS   10

// shared layout (floats): Keff[3600] | S[128*60] | C[128*60] | Om[64]
#define SMEM_FLOATS (3600 + BDIM*60 + BDIM*60 + 64)
#define SMEM_BYTES  (SMEM_FLOATS * 4)

__global__ __launch_bounds__(BDIM, 3)
void kuramoto_kernel(const float* __restrict__ theta,
                     const float* __restrict__ K,
                     const float* __restrict__ omega,
                     const float* __restrict__ p_Kg,
                     const float* __restrict__ p_cm,
                     const float* __restrict__ p_gate,
                     const float* __restrict__ p_csf,
                     const float* __restrict__ p_ds,
                     const float* __restrict__ p_rt,
                     float* __restrict__ out,
                     int B)
{
    extern __shared__ float smem[];
    float* sK  = smem;                 // K_eff = K * coupling_mod (ref-exact), broadcast reads
    float* sS  = sK + 3600;            // [tid][60] per-thread sin snapshot, stride 60
    float* sC  = sS + BDIM * 60;       // [tid][60] per-thread cos snapshot
    float* sOm = sC + BDIM * 60;       // raw omega [60]

    const int tid = threadIdx.x;
    const int b   = blockIdx.x * BDIM + tid;

    // ---- scalar factors, emulating the reference's fp32 op order exactly ----
    const float cf     = __fdiv_rn(1.0f, __fadd_rn(1.0f, __fmul_rn(p_csf[0], p_rt[0])));
    const float eff_dt = __fmul_rn(0.1f, cf);
    const float boost  = __fadd_rn(1.0f, __fmul_rn(p_gate[0], p_ds[0]));
    const float scale  = __fdiv_rn(__fmul_rn(p_Kg[0], boost), (float)N_OSC);

    // K_eff = K * coupling_mod, elementwise — bitwise identical to reference
    {
        const float cm = p_cm[0];
        for (int idx = tid; idx < 3600; idx += BDIM) sK[idx] = __fmul_rn(K[idx], cm);
    }
    if (tid < N_OSC) sOm[tid] = omega[tid];

    // ---- theta state in registers (all indices static after full unroll) ----
    float th[N_OSC];
    {
        const float4* th4 = (const float4*)(theta + (size_t)b * N_OSC);
        #pragma unroll
        for (int j4 = 0; j4 < 15; ++j4) {
            float4 v = th4[j4];
            th[4*j4 + 0] = v.x;
            th[4*j4 + 1] = v.y;
            th[4*j4 + 2] = v.z;
            th[4*j4 + 3] = v.w;
        }
    }
    __syncthreads();   // K/omega cooperative load

    float* sSr = sS + tid * 60;
    float* sCr = sC + tid * 60;

    for (int step = 0; step < STEPS; ++step) {
        // ---- snapshot sin/cos of current theta (fast path; coupling only) ----
        #pragma unroll
        for (int j4 = 0; j4 < 15; ++j4) {
            float4 sv, cv;
            __sincosf(th[4*j4 + 0], &sv.x, &cv.x);
            __sincosf(th[4*j4 + 1], &sv.y, &cv.y);
            __sincosf(th[4*j4 + 2], &sv.z, &cv.z);
            __sincosf(th[4*j4 + 3], &sv.w, &cv.w);
            *(float4*)&sSr[4*j4] = sv;
            *(float4*)&sCr[4*j4] = cv;
        }
        // no sync: each thread reads only its own rows; K is read-only

        // ---- matvec (Keff @ s, Keff @ c) in i-tiles of TI, then ref-exact update ----
        #pragma unroll
        for (int it = 0; it < NTILES; ++it) {
            const int i0 = it * TI;
            float accS[TI], accC[TI];
            #pragma unroll
            for (int u = 0; u < TI; ++u) { accS[u] = 0.f; accC[u] = 0.f; }

            for (int j4 = 0; j4 < 15; ++j4) {
                float4 s4 = *(const float4*)&sSr[4*j4];
                float4 c4 = *(const float4*)&sCr[4*j4];
                #pragma unroll
                for (int u = 0; u < TI; ++u) {
                    float4 k4 = *(const float4*)&sK[(i0 + u)*60 + 4*j4]; // warp-broadcast LDS.128
                    accS[u] = fmaf(k4.x, s4.x, fmaf(k4.y, s4.y,
                              fmaf(k4.z, s4.z, fmaf(k4.w, s4.w, accS[u]))));
                    accC[u] = fmaf(k4.x, c4.x, fmaf(k4.y, c4.y,
                              fmaf(k4.z, c4.z, fmaf(k4.w, c4.w, accC[u]))));
                }
            }

            // ---- epilogue: float2 si/ci reads (low-conflict), ref-exact update ----
            #pragma unroll
            for (int q = 0; q < TI/2; ++q) {
                const int i = i0 + 2*q;
                float2 s2 = *(const float2*)&sSr[i];
                float2 c2 = *(const float2*)&sCr[i];
                const float sv[2] = {s2.x, s2.y};
                const float cv[2] = {c2.x, c2.y};
                #pragma unroll
                for (int r = 0; r < 2; ++r) {
                    const int u  = 2*q + r;
                    const int ii = i + r;
                    // coupling = cos_i * sum(Keff*sin) - sin_i * sum(Keff*cos)
                    const float coupling = __fadd_rn(__fmul_rn(cv[r], accS[u]),
                                                     -__fmul_rn(sv[r], accC[u]));
                    // reference op order: t = th + eff_dt*(omega + scale*coupling)
                    const float tmp = __fadd_rn(sOm[ii], __fmul_rn(scale, coupling));
                    const float t   = __fadd_rn(th[ii], __fmul_rn(eff_dt, tmp));
                    // reference wrap: atan2(sin t, cos t) — precise libdevice
                    float sw, cw;
                    sincosf(t, &sw, &cw);
                    th[ii] = atan2f(sw, cw);
                }
            }
        }
    }

    // ---- output: theta [b*60 + j], then coherence at [B*60 + b] ----
    float ssum = 0.f, csum = 0.f;
    float4* o4 = (float4*)(out + (size_t)b * N_OSC);
    #pragma unroll
    for (int j4 = 0; j4 < 15; ++j4) {
        float4 v;
        v.x = th[4*j4 + 0];
        v.y = th[4*j4 + 1];
        v.z = th[4*j4 + 2];
        v.w = th[4*j4 + 3];
        o4[j4] = v;
        float s, c;
        sincosf(v.x, &s, &c); ssum += s; csum += c;
        sincosf(v.y, &s, &c); ssum += s; csum += c;
        sincosf(v.z, &s, &c); ssum += s; csum += c;
        sincosf(v.w, &s, &c); ssum += s; csum += c;
    }
    ssum = __fmul_rn(ssum, 1.0f / (float)N_OSC);
    csum = __fmul_rn(csum, 1.0f / (float)N_OSC);
    out[(size_t)B * N_OSC + b] = sqrtf(__fadd_rn(__fmul_rn(csum, csum),
                                                 __fmul_rn(ssum, ssum)));
}

extern "C" void kernel_launch(void* const* d_in, const int* in_sizes, int n_in,
                              void* d_out, int out_size)
{
    const float* theta = (const float*)d_in[0];
    const float* K     = (const float*)d_in[1];
    const float* omega = (const float*)d_in[2];
    const float* p_Kg   = (const float*)d_in[3];
    const float* p_cm   = (const float*)d_in[4];
    const float* p_gate = (const float*)d_in[5];
    const float* p_csf  = (const float*)d_in[6];
    const float* p_ds   = (const float*)d_in[7];
    const float* p_rt   = (const float*)d_in[8];
    float* out = (float*)d_out;

    const int B = in_sizes[0] / N_OSC;
    const int grid = B / BDIM;

    cudaFuncSetAttribute(kuramoto_kernel,
                         cudaFuncAttributeMaxDynamicSharedMemorySize, SMEM_BYTES);

    kuramoto_kernel<<<grid, BDIM, SMEM_BYTES>>>(
        theta, K, omega, p_Kg, p_cm, p_gate, p_csf, p_ds, p_rt, out, B);
}

// round 7
// speedup vs baseline: 1.0596x; 1.0596x over previous
#include <cuda_runtime.h>
#include <math_constants.h>

#define N_OSC   60
#define BDIM    128
#define TI      10          // i-tile size (accumulator block)
#define NTILES  6           // 60 / 10
#define STEPS   10

// shared layout (floats): Keff[3600] | Th[60*128] | Om[64]  = 45.4 KB
#define SMEM_FLOATS (3600 + 60*BDIM + 64)
#define SMEM_BYTES  (SMEM_FLOATS * 4)

__global__ __launch_bounds__(BDIM)
void kuramoto_kernel(const float* __restrict__ theta,
                     const float* __restrict__ K,
                     const float* __restrict__ omega,
                     const float* __restrict__ p_Kg,
                     const float* __restrict__ p_cm,
                     const float* __restrict__ p_gate,
                     const float* __restrict__ p_csf,
                     const float* __restrict__ p_ds,
                     const float* __restrict__ p_rt,
                     float* __restrict__ out,
                     int B)
{
    extern __shared__ float smem[];
    float* sK  = smem;                 // K_eff = K * coupling_mod (ref-exact), broadcast reads
    float* sTh = sK + 3600;            // [i][tid], stride BDIM (conflict-free scalar)
    float* sOm = sTh + 60 * BDIM;      // raw omega [60]

    const int tid = threadIdx.x;
    const int b   = blockIdx.x * BDIM + tid;

    // ---- scalar factors, emulating the reference's fp32 op order exactly ----
    const float cf     = __fdiv_rn(1.0f, __fadd_rn(1.0f, __fmul_rn(p_csf[0], p_rt[0])));
    const float eff_dt = __fmul_rn(0.1f, cf);
    const float boost  = __fadd_rn(1.0f, __fmul_rn(p_gate[0], p_ds[0]));
    const float scale  = __fdiv_rn(__fmul_rn(p_Kg[0], boost), (float)N_OSC);

    // K_eff = K * coupling_mod, elementwise — bitwise identical to reference
    {
        const float cm = p_cm[0];
        for (int idx = tid; idx < 3600; idx += BDIM) sK[idx] = __fmul_rn(K[idx], cm);
    }
    if (tid < N_OSC) sOm[tid] = omega[tid];

    // theta into smem [i][tid] (coalesced float4 in, conflict-free access after)
    {
        const float4* th4 = (const float4*)(theta + (size_t)b * N_OSC);
        #pragma unroll
        for (int j4 = 0; j4 < 15; ++j4) {
            float4 v = th4[j4];
            sTh[(4*j4 + 0)*BDIM + tid] = v.x;
            sTh[(4*j4 + 1)*BDIM + tid] = v.y;
            sTh[(4*j4 + 2)*BDIM + tid] = v.z;
            sTh[(4*j4 + 3)*BDIM + tid] = v.w;
        }
    }
    __syncthreads();   // K/omega cooperative load

    for (int step = 0; step < STEPS; ++step) {
        // ---- snapshot sin/cos of current theta into REGISTERS (static idx only) ----
        float s[N_OSC], c[N_OSC];
        #pragma unroll
        for (int j4 = 0; j4 < 15; ++j4) {
            __sincosf(sTh[(4*j4 + 0)*BDIM + tid], &s[4*j4 + 0], &c[4*j4 + 0]);
            __sincosf(sTh[(4*j4 + 1)*BDIM + tid], &s[4*j4 + 1], &c[4*j4 + 1]);
            __sincosf(sTh[(4*j4 + 2)*BDIM + tid], &s[4*j4 + 2], &c[4*j4 + 2]);
            __sincosf(sTh[(4*j4 + 3)*BDIM + tid], &s[4*j4 + 3], &c[4*j4 + 3]);
        }

        // ---- matvec (Keff @ s, Keff @ c): s/c are register operands now ----
        for (int it = 0; it < NTILES; ++it) {       // rolled: keeps code ~30 KB
            const int i0 = it * TI;
            float accS[TI], accC[TI];
            #pragma unroll
            for (int u = 0; u < TI; ++u) { accS[u] = 0.f; accC[u] = 0.f; }

            #pragma unroll
            for (int j4 = 0; j4 < 15; ++j4) {       // full unroll: static s/c indices
                #pragma unroll
                for (int u = 0; u < TI; ++u) {
                    float4 k4 = *(const float4*)&sK[(i0 + u)*60 + 4*j4]; // bcast LDS.128
                    accS[u] = fmaf(k4.x, s[4*j4+0], fmaf(k4.y, s[4*j4+1],
                              fmaf(k4.z, s[4*j4+2], fmaf(k4.w, s[4*j4+3], accS[u]))));
                    accC[u] = fmaf(k4.x, c[4*j4+0], fmaf(k4.y, c[4*j4+1],
                              fmaf(k4.z, c[4*j4+2], fmaf(k4.w, c[4*j4+3], accC[u]))));
                }
            }

            // ---- epilogue: recompute si/ci from pre-update theta (bitwise ==
            // snapshot, avoids dynamic register-array indexing), ref-exact update
            #pragma unroll
            for (int u = 0; u < TI; ++u) {
                const int i = i0 + u;
                const float thi = sTh[i*BDIM + tid];   // pre-update value
                float si, ci;
                __sincosf(thi, &si, &ci);              // == s[i], c[i] bitwise
                // coupling = cos_i * sum(Keff*sin) - sin_i * sum(Keff*cos)
                const float coupling = __fadd_rn(__fmul_rn(ci, accS[u]),
                                                 -__fmul_rn(si, accC[u]));
                // reference op order: t = th + eff_dt*(omega + scale*coupling)
                const float tmp = __fadd_rn(sOm[i], __fmul_rn(scale, coupling));
                const float t   = __fadd_rn(thi, __fmul_rn(eff_dt, tmp));
                // reference wrap: atan2(sin t, cos t) — precise libdevice
                float sw, cw;
                sincosf(t, &sw, &cw);
                sTh[i*BDIM + tid] = atan2f(sw, cw);
            }
        }
    }

    // ---- output: theta [b*60 + j], then coherence at [B*60 + b] ----
    float ssum = 0.f, csum = 0.f;
    float4* o4 = (float4*)(out + (size_t)b * N_OSC);
    #pragma unroll
    for (int j4 = 0; j4 < 15; ++j4) {
        float4 v;
        v.x = sTh[(4*j4 + 0)*BDIM + tid];
        v.y = sTh[(4*j4 + 1)*BDIM + tid];
        v.z = sTh[(4*j4 + 2)*BDIM + tid];
        v.w = sTh[(4*j4 + 3)*BDIM + tid];
        o4[j4] = v;
        float sv, cv;
        sincosf(v.x, &sv, &cv); ssum += sv; csum += cv;
        sincosf(v.y, &sv, &cv); ssum += sv; csum += cv;
        sincosf(v.z, &sv, &cv); ssum += sv; csum += cv;
        sincosf(v.w, &sv, &cv); ssum += sv; csum += cv;
    }
    ssum = __fmul_rn(ssum, 1.0f / (float)N_OSC);
    csum = __fmul_rn(csum, 1.0f / (float)N_OSC);
    out[(size_t)B * N_OSC + b] = sqrtf(__fadd_rn(__fmul_rn(csum, csum),
                                                 __fmul_rn(ssum, ssum)));
}

extern "C" void kernel_launch(void* const* d_in, const int* in_sizes, int n_in,
                              void* d_out, int out_size)
{
    const float* theta = (const float*)d_in[0];
    const float* K     = (const float*)d_in[1];
    const float* omega = (const float*)d_in[2];
    const float* p_Kg   = (const float*)d_in[3];
    const float* p_cm   = (const float*)d_in[4];
    const float* p_gate = (const float*)d_in[5];
    const float* p_csf  = (const float*)d_in[6];
    const float* p_ds   = (const float*)d_in[7];
    const float* p_rt   = (const float*)d_in[8];
    float* out = (float*)d_out;

    const int B = in_sizes[0] / N_OSC;
    const int grid = B / BDIM;

    cudaFuncSetAttribute(kuramoto_kernel,
                         cudaFuncAttributeMaxDynamicSharedMemorySize, SMEM_BYTES);

    kuramoto_kernel<<<grid, BDIM, SMEM_BYTES>>>(
        theta, K, omega, p_Kg, p_cm, p_gate, p_csf, p_ds, p_rt, out, B);
}

// round 9
// speedup vs baseline: 2.1435x; 2.0230x over previous
#include <cuda_runtime.h>
#include <cstdint>

#define N_OSC 60
#define BDIM  128
#define NB    32        // batches per CTA
#define IQ    15        // i's (and snapshot j's) per thread
#define STEPS 10
#define TH_STRIDE 33    // padded theta row stride (banks)

// smem floats: K[3600] | S[32*60] | C[32*60] | Th[60*33] | Om[64]
#define SMEM_FLOATS (3600 + NB*60 + NB*60 + 60*TH_STRIDE + 64)
#define SMEM_BYTES  (SMEM_FLOATS * 4)

__global__ __launch_bounds__(BDIM)
void kuramoto_kernel(const float* __restrict__ theta,
                     const float* __restrict__ K,
                     const float* __restrict__ omega,
                     const float* __restrict__ p_Kg,
                     const float* __restrict__ p_cm,
                     const float* __restrict__ p_gate,
                     const float* __restrict__ p_csf,
                     const float* __restrict__ p_ds,
                     const float* __restrict__ p_rt,
                     float* __restrict__ out,
                     int B)
{
    extern __shared__ float smem[];
    float* sK  = smem;                    // K_eff (ref-exact), broadcast-ish reads
    float* sS  = sK  + 3600;              // [batch][60]
    float* sC  = sS  + NB * 60;           // [batch][60]
    float* sTh = sC  + NB * 60;           // [i][batch], stride 33
    float* sOm = sTh + 60 * TH_STRIDE;    // raw omega

    const int tid = threadIdx.x;
    const int q   = tid & 3;              // quarter: owns i,j in [15q, 15q+15)
    const int bl  = tid >> 2;             // local batch 0..31
    const int i0  = q * IQ;
    const int bg0 = blockIdx.x * NB;      // global batch base of this CTA

    // ---- scalar factors, emulating the reference's fp32 op order exactly ----
    const float cf     = __fdiv_rn(1.0f, __fadd_rn(1.0f, __fmul_rn(p_csf[0], p_rt[0])));
    const float eff_dt = __fmul_rn(0.1f, cf);
    const float boost  = __fadd_rn(1.0f, __fmul_rn(p_gate[0], p_ds[0]));
    const float scale  = __fdiv_rn(__fmul_rn(p_Kg[0], boost), (float)N_OSC);

    // K_eff = K * coupling_mod, elementwise — bitwise identical to reference
    {
        const float cm = p_cm[0];
        for (int idx = tid; idx < 3600; idx += BDIM) sK[idx] = __fmul_rn(K[idx], cm);
    }
    if (tid < N_OSC) sOm[tid] = omega[tid];

    // ---- theta load: 32 batches x 15 float4, cooperative ----
    {
        const float4* th4 = (const float4*)(theta + (size_t)bg0 * N_OSC);
        #pragma unroll
        for (int l = 0; l < (NB*15)/BDIM; ++l) {        // 480/128 = 3.75 -> 3 + tail
            const int idx = l * BDIM + tid;
            float4 v = th4[idx];
            const int b = idx / 15, j4 = idx % 15;
            sTh[(4*j4 + 0)*TH_STRIDE + b] = v.x;
            sTh[(4*j4 + 1)*TH_STRIDE + b] = v.y;
            sTh[(4*j4 + 2)*TH_STRIDE + b] = v.z;
            sTh[(4*j4 + 3)*TH_STRIDE + b] = v.w;
        }
        const int idx = 3 * BDIM + tid;                  // tail
        if (idx < NB*15) {
            float4 v = th4[idx];
            const int b = idx / 15, j4 = idx % 15;
            sTh[(4*j4 + 0)*TH_STRIDE + b] = v.x;
            sTh[(4*j4 + 1)*TH_STRIDE + b] = v.y;
            sTh[(4*j4 + 2)*TH_STRIDE + b] = v.z;
            sTh[(4*j4 + 3)*TH_STRIDE + b] = v.w;
        }
    }
    __syncthreads();   // K/omega/theta cooperative load

    float* sSr = sS + bl * 60;
    float* sCr = sC + bl * 60;

    for (int step = 0; step < STEPS; ++step) {
        // ---- snapshot: this thread fills j in [i0, i0+15) of its batch row ----
        #pragma unroll
        for (int e = 0; e < IQ; ++e) {
            const int j = i0 + e;
            float s, c;
            __sincosf(sTh[j*TH_STRIDE + bl], &s, &c);
            sSr[j] = s;
            sCr[j] = c;
        }
        __syncwarp();   // batch's 4 threads are in this warp

        // ---- matvec rows i0..i0+14 over all 60 j (same j-order/nesting as R2) ----
        float accS[IQ], accC[IQ];
        #pragma unroll
        for (int u = 0; u < IQ; ++u) { accS[u] = 0.f; accC[u] = 0.f; }

        #pragma unroll
        for (int j4 = 0; j4 < 15; ++j4) {
            float4 s4 = *(const float4*)&sSr[4*j4];
            float4 c4 = *(const float4*)&sCr[4*j4];
            #pragma unroll
            for (int u = 0; u < IQ; ++u) {
                float4 k4 = *(const float4*)&sK[(i0 + u)*60 + 4*j4];
                accS[u] = fmaf(k4.x, s4.x, fmaf(k4.y, s4.y,
                          fmaf(k4.z, s4.z, fmaf(k4.w, s4.w, accS[u]))));
                accC[u] = fmaf(k4.x, c4.x, fmaf(k4.y, c4.y,
                          fmaf(k4.z, c4.z, fmaf(k4.w, c4.w, accC[u]))));
            }
        }

        // ---- epilogue: ref-exact update + precise libdevice wrap ----
        #pragma unroll
        for (int u = 0; u < IQ; ++u) {
            const int i = i0 + u;
            const float si = sSr[i];
            const float ci = sCr[i];
            // coupling = cos_i * sum(Keff*sin) - sin_i * sum(Keff*cos)
            const float coupling = __fadd_rn(__fmul_rn(ci, accS[u]),
                                             -__fmul_rn(si, accC[u]));
            // reference op order: t = th + eff_dt*(omega + scale*coupling)
            const float tmp = __fadd_rn(sOm[i], __fmul_rn(scale, coupling));
            const float t   = __fadd_rn(sTh[i*TH_STRIDE + bl], __fmul_rn(eff_dt, tmp));
            // reference wrap: atan2(sin t, cos t) — precise libdevice
            float sw, cw;
            sincosf(t, &sw, &cw);
            sTh[i*TH_STRIDE + bl] = atan2f(sw, cw);
        }
        __syncwarp();   // publish updated theta to batch partners
    }

    // ---- coherence: quarter partial sums (precise fns), shfl-combine ----
    float ssum = 0.f, csum = 0.f;
    #pragma unroll
    for (int e = 0; e < IQ; ++e) {
        float s, c;
        sincosf(sTh[(i0 + e)*TH_STRIDE + bl], &s, &c);
        ssum += s; csum += c;
    }
    ssum += __shfl_xor_sync(0xFFFFFFFFu, ssum, 1);
    csum += __shfl_xor_sync(0xFFFFFFFFu, csum, 1);
    ssum += __shfl_xor_sync(0xFFFFFFFFu, ssum, 2);
    csum += __shfl_xor_sync(0xFFFFFFFFu, csum, 2);
    if (q == 0) {
        const float sm = __fmul_rn(ssum, 1.0f / (float)N_OSC);
        const float cm2 = __fmul_rn(csum, 1.0f / (float)N_OSC);
        out[(size_t)B * N_OSC + bg0 + bl] =
            sqrtf(__fadd_rn(__fmul_rn(cm2, cm2), __fmul_rn(sm, sm)));
    }

    // ---- theta out: cooperative float4 gather (needs cross-warp visibility) ----
    __syncthreads();
    {
        float4* o4 = (float4*)(out + (size_t)bg0 * N_OSC);
        #pragma unroll
        for (int l = 0; l < (NB*15)/BDIM; ++l) {
            const int idx = l * BDIM + tid;
            const int b = idx / 15, j4 = idx % 15;
            float4 v;
            v.x = sTh[(4*j4 + 0)*TH_STRIDE + b];
            v.y = sTh[(4*j4 + 1)*TH_STRIDE + b];
            v.z = sTh[(4*j4 + 2)*TH_STRIDE + b];
            v.w = sTh[(4*j4 + 3)*TH_STRIDE + b];
            o4[idx] = v;
        }
        const int idx = 3 * BDIM + tid;                  // tail
        if (idx < NB*15) {
            const int b = idx / 15, j4 = idx % 15;
            float4 v;
            v.x = sTh[(4*j4 + 0)*TH_STRIDE + b];
            v.y = sTh[(4*j4 + 1)*TH_STRIDE + b];
            v.z = sTh[(4*j4 + 2)*TH_STRIDE + b];
            v.w = sTh[(4*j4 + 3)*TH_STRIDE + b];
            o4[idx] = v;
        }
    }
}

extern "C" void kernel_launch(void* const* d_in, const int* in_sizes, int n_in,
                              void* d_out, int out_size)
{
    const float* theta = (const float*)d_in[0];
    const float* K     = (const float*)d_in[1];
    const float* omega = (const float*)d_in[2];
    const float* p_Kg   = (const float*)d_in[3];
    const float* p_cm   = (const float*)d_in[4];
    const float* p_gate = (const float*)d_in[5];
    const float* p_csf  = (const float*)d_in[6];
    const float* p_ds   = (const float*)d_in[7];
    const float* p_rt   = (const float*)d_in[8];
    float* out = (float*)d_out;

    const int B = in_sizes[0] / N_OSC;
    const int grid = B / NB;

    cudaFuncSetAttribute(kuramoto_kernel,
                         cudaFuncAttributeMaxDynamicSharedMemorySize, SMEM_BYTES);

    kuramoto_kernel<<<grid, BDIM, SMEM_BYTES>>>(
        theta, K, omega, p_Kg, p_cm, p_gate, p_csf, p_ds, p_rt, out, B);
}

// round 10
// speedup vs baseline: 2.1985x; 1.0257x over previous
#include <cuda_runtime.h>
#include <cstdint>

#define N_OSC 60
#define BDIM  128
#define NB    32        // batches per CTA
#define IQ    15        // i's (and snapshot j's) per thread
#define STEPS 10
#define TH_STRIDE 33    // padded theta row stride (banks)

// smem floats: K[3600] | S[32*60] | C[32*60] | Th[60*33] | Om[64]
#define SMEM_FLOATS (3600 + NB*60 + NB*60 + 60*TH_STRIDE + 64)
#define SMEM_BYTES  (SMEM_FLOATS * 4)

__global__ __launch_bounds__(BDIM, 6)
void kuramoto_kernel(const float* __restrict__ theta,
                     const float* __restrict__ K,
                     const float* __restrict__ omega,
                     const float* __restrict__ p_Kg,
                     const float* __restrict__ p_cm,
                     const float* __restrict__ p_gate,
                     const float* __restrict__ p_csf,
                     const float* __restrict__ p_ds,
                     const float* __restrict__ p_rt,
                     float* __restrict__ out,
                     int B)
{
    extern __shared__ float smem[];
    float* sK  = smem;                    // K_eff (ref-exact)
    float* sS  = sK  + 3600;              // [batch][60] sin snapshot
    float* sC  = sS  + NB * 60;           // [batch][60] cos snapshot
    float* sTh = sC  + NB * 60;           // [i][batch], stride 33
    float* sOm = sTh + 60 * TH_STRIDE;    // raw omega

    const int tid = threadIdx.x;
    const int q   = tid & 3;              // quarter: owns i,j in [15q, 15q+15)
    const int bl  = tid >> 2;             // local batch 0..31
    const int i0  = q * IQ;
    const int bg0 = blockIdx.x * NB;      // global batch base of this CTA

    // ---- scalar factors, emulating the reference's fp32 op order exactly ----
    const float cf     = __fdiv_rn(1.0f, __fadd_rn(1.0f, __fmul_rn(p_csf[0], p_rt[0])));
    const float eff_dt = __fmul_rn(0.1f, cf);
    const float boost  = __fadd_rn(1.0f, __fmul_rn(p_gate[0], p_ds[0]));
    const float scale  = __fdiv_rn(__fmul_rn(p_Kg[0], boost), (float)N_OSC);

    // K_eff = K * coupling_mod, elementwise — bitwise identical to reference
    {
        const float cm = p_cm[0];
        for (int idx = tid; idx < 3600; idx += BDIM) sK[idx] = __fmul_rn(K[idx], cm);
    }
    if (tid < N_OSC) sOm[tid] = omega[tid];

    // ---- theta load: 32 batches x 15 float4, cooperative ----
    {
        const float4* th4 = (const float4*)(theta + (size_t)bg0 * N_OSC);
        #pragma unroll
        for (int l = 0; l < (NB*15)/BDIM; ++l) {        // 3 full rounds
            const int idx = l * BDIM + tid;
            float4 v = th4[idx];
            const int b = idx / 15, j4 = idx % 15;
            sTh[(4*j4 + 0)*TH_STRIDE + b] = v.x;
            sTh[(4*j4 + 1)*TH_STRIDE + b] = v.y;
            sTh[(4*j4 + 2)*TH_STRIDE + b] = v.z;
            sTh[(4*j4 + 3)*TH_STRIDE + b] = v.w;
        }
        const int idx = 3 * BDIM + tid;                  // tail
        if (idx < NB*15) {
            float4 v = th4[idx];
            const int b = idx / 15, j4 = idx % 15;
            sTh[(4*j4 + 0)*TH_STRIDE + b] = v.x;
            sTh[(4*j4 + 1)*TH_STRIDE + b] = v.y;
            sTh[(4*j4 + 2)*TH_STRIDE + b] = v.z;
            sTh[(4*j4 + 3)*TH_STRIDE + b] = v.w;
        }
    }
    __syncthreads();   // K/omega/theta cooperative load

    float* sSr = sS + bl * 60;
    float* sCr = sC + bl * 60;

    // ---- step-0 snapshot only (later steps reuse epilogue's sinf/cosf) ----
    #pragma unroll
    for (int e = 0; e < IQ; ++e) {
        const int j = i0 + e;
        float s, c;
        __sincosf(sTh[j*TH_STRIDE + bl], &s, &c);
        sSr[j] = s;
        sCr[j] = c;
    }
    __syncwarp();

    for (int step = 0; step < STEPS; ++step) {
        // ---- matvec rows i0..i0+14 over all 60 j (same nesting as R9) ----
        float accS[IQ], accC[IQ];
        #pragma unroll
        for (int u = 0; u < IQ; ++u) { accS[u] = 0.f; accC[u] = 0.f; }

        #pragma unroll
        for (int j4 = 0; j4 < 15; ++j4) {
            float4 s4 = *(const float4*)&sSr[4*j4];
            float4 c4 = *(const float4*)&sCr[4*j4];
            #pragma unroll
            for (int u = 0; u < IQ; ++u) {
                float4 k4 = *(const float4*)&sK[(i0 + u)*60 + 4*j4];
                accS[u] = fmaf(k4.x, s4.x, fmaf(k4.y, s4.y,
                          fmaf(k4.z, s4.z, fmaf(k4.w, s4.w, accS[u]))));
                accC[u] = fmaf(k4.x, c4.x, fmaf(k4.y, c4.y,
                          fmaf(k4.z, c4.z, fmaf(k4.w, c4.w, accC[u]))));
            }
        }
        __syncwarp();   // partners done reading s/c before we overwrite below

        // ---- epilogue: ref-exact update + precise wrap; publish s/c for next ----
        #pragma unroll
        for (int u = 0; u < IQ; ++u) {
            const int i = i0 + u;
            const float si = sSr[i];
            const float ci = sCr[i];
            // coupling = cos_i * sum(Keff*sin) - sin_i * sum(Keff*cos)
            const float coupling = __fadd_rn(__fmul_rn(ci, accS[u]),
                                             -__fmul_rn(si, accC[u]));
            // reference op order: t = th + eff_dt*(omega + scale*coupling)
            const float tmp = __fadd_rn(sOm[i], __fmul_rn(scale, coupling));
            const float t   = __fadd_rn(sTh[i*TH_STRIDE + bl], __fmul_rn(eff_dt, tmp));
            // reference wrap: atan2(sin t, cos t) — precise libdevice
            float sw, cw;
            sincosf(t, &sw, &cw);
            sTh[i*TH_STRIDE + bl] = atan2f(sw, cw);
            // next-step snapshot: sinf(t)/cosf(t) ≈ sin/cos of wrapped theta
            // (|t - wrapped| ~ 1 ulp → err ~2e-7, tighter than __sincosf's 3.6e-7)
            sSr[i] = sw;
            sCr[i] = cw;
        }
        __syncwarp();   // publish s/c (and theta) to batch partners
    }

    // ---- coherence from final s/c snapshots (err ~2e-7, within tolerance) ----
    float ssum = 0.f, csum = 0.f;
    #pragma unroll
    for (int e = 0; e < IQ; ++e) {
        ssum += sSr[i0 + e];
        csum += sCr[i0 + e];
    }
    ssum += __shfl_xor_sync(0xFFFFFFFFu, ssum, 1);
    csum += __shfl_xor_sync(0xFFFFFFFFu, csum, 1);
    ssum += __shfl_xor_sync(0xFFFFFFFFu, ssum, 2);
    csum += __shfl_xor_sync(0xFFFFFFFFu, csum, 2);
    if (q == 0) {
        const float sm  = __fmul_rn(ssum, 1.0f / (float)N_OSC);
        const float cm2 = __fmul_rn(csum, 1.0f / (float)N_OSC);
        out[(size_t)B * N_OSC + bg0 + bl] =
            sqrtf(__fadd_rn(__fmul_rn(cm2, cm2), __fmul_rn(sm, sm)));
    }

    // ---- theta out: cooperative float4 gather ----
    __syncthreads();
    {
        float4* o4 = (float4*)(out + (size_t)bg0 * N_OSC);
        #pragma unroll
        for (int l = 0; l < (NB*15)/BDIM; ++l) {
            const int idx = l * BDIM + tid;
            const int b = idx / 15, j4 = idx % 15;
            float4 v;
            v.x = sTh[(4*j4 + 0)*TH_STRIDE + b];
            v.y = sTh[(4*j4 + 1)*TH_STRIDE + b];
            v.z = sTh[(4*j4 + 2)*TH_STRIDE + b];
            v.w = sTh[(4*j4 + 3)*TH_STRIDE + b];
            o4[idx] = v;
        }
        const int idx = 3 * BDIM + tid;                  // tail
        if (idx < NB*15) {
            const int b = idx / 15, j4 = idx % 15;
            float4 v;
            v.x = sTh[(4*j4 + 0)*TH_STRIDE + b];
            v.y = sTh[(4*j4 + 1)*TH_STRIDE + b];
            v.z = sTh[(4*j4 + 2)*TH_STRIDE + b];
            v.w = sTh[(4*j4 + 3)*TH_STRIDE + b];
            o4[idx] = v;
        }
    }
}

extern "C" void kernel_launch(void* const* d_in, const int* in_sizes, int n_in,
                              void* d_out, int out_size)
{
    const float* theta = (const float*)d_in[0];
    const float* K     = (const float*)d_in[1];
    const float* omega = (const float*)d_in[2];
    const float* p_Kg   = (const float*)d_in[3];
    const float* p_cm   = (const float*)d_in[4];
    const float* p_gate = (const float*)d_in[5];
    const float* p_csf  = (const float*)d_in[6];
    const float* p_ds   = (const float*)d_in[7];
    const float* p_rt   = (const float*)d_in[8];
    float* out = (float*)d_out;

    const int B = in_sizes[0] / N_OSC;
    const int grid = B / NB;

    cudaFuncSetAttribute(kuramoto_kernel,
                         cudaFuncAttributeMaxDynamicSharedMemorySize, SMEM_BYTES);

    kuramoto_kernel<<<grid, BDIM, SMEM_BYTES>>>(
        theta, K, omega, p_Kg, p_cm, p_gate, p_csf, p_ds, p_rt, out, B);
}

// round 11
// speedup vs baseline: 2.3196x; 1.0551x over previous
#include <cuda_runtime.h>
#include <cstdint>

#define N_OSC 60
#define BDIM  128
#define NB    32        // batches per CTA (= lanes)
#define IQ    15        // i's (and snapshot j's) per warp-quarter
#define STEPS 10
#define TH_STRIDE 33    // padded theta row stride (banks)

// smem floats: K[3600] | S[32*60] | C[32*60] | Th[60*33] | Om[64]
#define SMEM_FLOATS (3600 + NB*60 + NB*60 + 60*TH_STRIDE + 64)
#define SMEM_BYTES  (SMEM_FLOATS * 4)

__global__ __launch_bounds__(BDIM)
void kuramoto_kernel(const float* __restrict__ theta,
                     const float* __restrict__ K,
                     const float* __restrict__ omega,
                     const float* __restrict__ p_Kg,
                     const float* __restrict__ p_cm,
                     const float* __restrict__ p_gate,
                     const float* __restrict__ p_csf,
                     const float* __restrict__ p_ds,
                     const float* __restrict__ p_rt,
                     float* __restrict__ out,
                     int B)
{
    extern __shared__ float smem[];
    float* sK  = smem;                    // K_eff (ref-exact); scratch after loop
    float* sS  = sK  + 3600;              // [batch][60] sin snapshot
    float* sC  = sS  + NB * 60;           // [batch][60] cos snapshot
    float* sTh = sC  + NB * 60;           // [i][batch], stride 33
    float* sOm = sTh + 60 * TH_STRIDE;    // raw omega

    const int tid  = threadIdx.x;
    const int wid  = tid >> 5;            // quarter: owns i,j in [15*wid, 15*wid+15)
    const int lane = tid & 31;            // batch 0..31
    const int i0   = wid * IQ;
    const int bg0  = blockIdx.x * NB;     // global batch base of this CTA

    // ---- scalar factors, emulating the reference's fp32 op order exactly ----
    const float cf     = __fdiv_rn(1.0f, __fadd_rn(1.0f, __fmul_rn(p_csf[0], p_rt[0])));
    const float eff_dt = __fmul_rn(0.1f, cf);
    const float boost  = __fadd_rn(1.0f, __fmul_rn(p_gate[0], p_ds[0]));
    const float scale  = __fdiv_rn(__fmul_rn(p_Kg[0], boost), (float)N_OSC);

    // K_eff = K * coupling_mod, elementwise — bitwise identical to reference
    {
        const float cm = p_cm[0];
        for (int idx = tid; idx < 3600; idx += BDIM) sK[idx] = __fmul_rn(K[idx], cm);
    }
    if (tid < N_OSC) sOm[tid] = omega[tid];

    // ---- theta load: 32 batches x 15 float4, cooperative ----
    {
        const float4* th4 = (const float4*)(theta + (size_t)bg0 * N_OSC);
        #pragma unroll
        for (int l = 0; l < (NB*15)/BDIM; ++l) {        // 3 full rounds
            const int idx = l * BDIM + tid;
            float4 v = th4[idx];
            const int b = idx / 15, j4 = idx % 15;
            sTh[(4*j4 + 0)*TH_STRIDE + b] = v.x;
            sTh[(4*j4 + 1)*TH_STRIDE + b] = v.y;
            sTh[(4*j4 + 2)*TH_STRIDE + b] = v.z;
            sTh[(4*j4 + 3)*TH_STRIDE + b] = v.w;
        }
        const int idx = 3 * BDIM + tid;                  // tail
        if (idx < NB*15) {
            float4 v = th4[idx];
            const int b = idx / 15, j4 = idx % 15;
            sTh[(4*j4 + 0)*TH_STRIDE + b] = v.x;
            sTh[(4*j4 + 1)*TH_STRIDE + b] = v.y;
            sTh[(4*j4 + 2)*TH_STRIDE + b] = v.z;
            sTh[(4*j4 + 3)*TH_STRIDE + b] = v.w;
        }
    }
    __syncthreads();   // K/omega/theta cooperative load

    float* sSr = sS + lane * 60;
    float* sCr = sC + lane * 60;

    // ---- step-0 snapshot: this warp fills j in [i0, i0+15) of batch 'lane' ----
    #pragma unroll
    for (int e = 0; e < IQ; ++e) {
        const int j = i0 + e;
        float s, c;
        __sincosf(sTh[j*TH_STRIDE + lane], &s, &c);
        sSr[j] = s;
        sCr[j] = c;
    }
    __syncthreads();   // publish snapshot across warps

    for (int step = 0; step < STEPS; ++step) {
        // ---- matvec rows i0..i0+14 over all 60 j ----
        // k4 address is UNIFORM across the warp -> broadcast LDS (1 wavefront)
        float accS[IQ], accC[IQ];
        #pragma unroll
        for (int u = 0; u < IQ; ++u) { accS[u] = 0.f; accC[u] = 0.f; }

        #pragma unroll
        for (int j4 = 0; j4 < 15; ++j4) {
            float4 s4 = *(const float4*)&sSr[4*j4];
            float4 c4 = *(const float4*)&sCr[4*j4];
            #pragma unroll
            for (int u = 0; u < IQ; ++u) {
                float4 k4 = *(const float4*)&sK[(i0 + u)*60 + 4*j4]; // warp-uniform
                accS[u] = fmaf(k4.x, s4.x, fmaf(k4.y, s4.y,
                          fmaf(k4.z, s4.z, fmaf(k4.w, s4.w, accS[u]))));
                accC[u] = fmaf(k4.x, c4.x, fmaf(k4.y, c4.y,
                          fmaf(k4.z, c4.z, fmaf(k4.w, c4.w, accC[u]))));
            }
        }
        __syncthreads();   // all warps done reading s/c before overwrite

        // ---- epilogue: ref-exact update + precise wrap; publish s/c for next ----
        #pragma unroll
        for (int u = 0; u < IQ; ++u) {
            const int i = i0 + u;
            const float si = sSr[i];
            const float ci = sCr[i];
            // coupling = cos_i * sum(Keff*sin) - sin_i * sum(Keff*cos)
            const float coupling = __fadd_rn(__fmul_rn(ci, accS[u]),
                                             -__fmul_rn(si, accC[u]));
            // reference op order: t = th + eff_dt*(omega + scale*coupling)
            const float tmp = __fadd_rn(sOm[i], __fmul_rn(scale, coupling));
            const float t   = __fadd_rn(sTh[i*TH_STRIDE + lane], __fmul_rn(eff_dt, tmp));
            // reference wrap: atan2(sin t, cos t) — precise libdevice
            float sw, cw;
            sincosf(t, &sw, &cw);
            sTh[i*TH_STRIDE + lane] = atan2f(sw, cw);
            // next-step snapshot: sinf(t)/cosf(t) (~2e-7 vs wrapped; tolerant path)
            sSr[i] = sw;
            sCr[i] = cw;
        }
        __syncthreads();   // publish s/c + theta across warps
    }

    // ---- coherence: per-quarter partials -> smem scratch (reuse dead sK) ----
    {
        float ssum = 0.f, csum = 0.f;
        #pragma unroll
        for (int e = 0; e < IQ; ++e) {
            ssum += sSr[i0 + e];
            csum += sCr[i0 + e];
        }
        float* redS = sK;          // 128 floats scratch (K dead after last matvec)
        float* redC = sK + 128;
        redS[wid*32 + lane] = ssum;
        redC[wid*32 + lane] = csum;
    }
    __syncthreads();
    if (wid == 0) {
        float ssum = sK[lane] + sK[32 + lane] + sK[64 + lane] + sK[96 + lane];
        float csum = sK[128 + lane] + sK[160 + lane] + sK[192 + lane] + sK[224 + lane];
        const float sm  = __fmul_rn(ssum, 1.0f / (float)N_OSC);
        const float cm2 = __fmul_rn(csum, 1.0f / (float)N_OSC);
        out[(size_t)B * N_OSC + bg0 + lane] =
            sqrtf(__fadd_rn(__fmul_rn(cm2, cm2), __fmul_rn(sm, sm)));
    }

    // ---- theta out: cooperative float4 gather ----
    {
        float4* o4 = (float4*)(out + (size_t)bg0 * N_OSC);
        #pragma unroll
        for (int l = 0; l < (NB*15)/BDIM; ++l) {
            const int idx = l * BDIM + tid;
            const int b = idx / 15, j4 = idx % 15;
            float4 v;
            v.x = sTh[(4*j4 + 0)*TH_STRIDE + b];
            v.y = sTh[(4*j4 + 1)*TH_STRIDE + b];
            v.z = sTh[(4*j4 + 2)*TH_STRIDE + b];
            v.w = sTh[(4*j4 + 3)*TH_STRIDE + b];
            o4[idx] = v;
        }
        const int idx = 3 * BDIM + tid;                  // tail
        if (idx < NB*15) {
            const int b = idx / 15, j4 = idx % 15;
            float4 v;
            v.x = sTh[(4*j4 + 0)*TH_STRIDE + b];
            v.y = sTh[(4*j4 + 1)*TH_STRIDE + b];
            v.z = sTh[(4*j4 + 2)*TH_STRIDE + b];
            v.w = sTh[(4*j4 + 3)*TH_STRIDE + b];
            o4[idx] = v;
        }
    }
}

extern "C" void kernel_launch(void* const* d_in, const int* in_sizes, int n_in,
                              void* d_out, int out_size)
{
    const float* theta = (const float*)d_in[0];
    const float* K     = (const float*)d_in[1];
    const float* omega = (const float*)d_in[2];
    const float* p_Kg   = (const float*)d_in[3];
    const float* p_cm   = (const float*)d_in[4];
    const float* p_gate = (const float*)d_in[5];
    const float* p_csf  = (const float*)d_in[6];
    const float* p_ds   = (const float*)d_in[7];
    const float* p_rt   = (const float*)d_in[8];
    float* out = (float*)d_out;

    const int B = in_sizes[0] / N_OSC;
    const int grid = B / NB;

    cudaFuncSetAttribute(kuramoto_kernel,
                         cudaFuncAttributeMaxDynamicSharedMemorySize, SMEM_BYTES);

    kuramoto_kernel<<<grid, BDIM, SMEM_BYTES>>>(
        theta, K, omega, p_Kg, p_cm, p_gate, p_csf, p_ds, p_rt, out, B);
}